// round 7
// baseline (speedup 1.0000x reference)
#include <cuda_runtime.h>
#include <cuda_bf16.h>
#include <cstdint>

typedef __nv_bfloat16 bf;

#define NB 16
#define SS_ 1024
#define DD_ 1024
#define MTOT (NB*SS_)              // 16384
#define PLANE (MTOT*DD_)           // 16,777,216
#define BATSTR (SS_*DD_)           // 1,048,576

// ---------------- device scratch (statics; no allocation allowed) ----------
__device__ bf g_xh[6][PLANE];      __device__ bf g_xl[6][PLANE];      // split inputs
__device__ bf g_wh[6][DD_*DD_];    __device__ bf g_wl[6][DD_*DD_];    // split weights
__device__ bf g_ph[6][PLANE];      __device__ bf g_pl[6][PLANE];      // proj outputs
__device__ bf g_th[3][PLANE];      __device__ bf g_tl[3][PLANE];      // transposed kr,vr,vi
__device__ bf g_ah[PLANE];         __device__ bf g_al[PLANE];         // split attn
__device__ float g_att[PLANE];     // raw scores
__device__ float g_or[PLANE];      __device__ float g_oi[PLANE];

// ---------------- helpers ---------------------------------------------------
__device__ __forceinline__ uint32_t smem_u32(const void* p) {
    uint32_t a;
    asm("{ .reg .u64 t; cvta.to.shared.u64 t, %1; cvt.u32.u64 %0, t; }"
        : "=r"(a) : "l"(p));
    return a;
}
__device__ __forceinline__ void cp16(uint32_t s, const void* g) {
    asm volatile("cp.async.cg.shared.global [%0], [%1], 16;" :: "r"(s), "l"(g));
}
#define CP_COMMIT() asm volatile("cp.async.commit_group;" ::: "memory")
#define CP_WAIT1()  asm volatile("cp.async.wait_group 1;" ::: "memory")
#define CP_WAIT0()  asm volatile("cp.async.wait_group 0;" ::: "memory")

__device__ __forceinline__ void ldm4(uint32_t* r, uint32_t addr) {
    asm volatile("ldmatrix.sync.aligned.m8n8.x4.shared.b16 {%0,%1,%2,%3}, [%4];"
        : "=r"(r[0]), "=r"(r[1]), "=r"(r[2]), "=r"(r[3]) : "r"(addr));
}
__device__ __forceinline__ void mma16816(float* d, const uint32_t* a, const uint32_t* b) {
    asm volatile(
        "mma.sync.aligned.m16n8k16.row.col.f32.bf16.bf16.f32 "
        "{%0,%1,%2,%3}, {%4,%5,%6,%7}, {%8,%9}, {%0,%1,%2,%3};"
        : "+f"(d[0]), "+f"(d[1]), "+f"(d[2]), "+f"(d[3])
        : "r"(a[0]), "r"(a[1]), "r"(a[2]), "r"(a[3]), "r"(b[0]), "r"(b[1]));
}

// ---------------- tensor-core split-bf16 NT GEMM ----------------------------
// C[m,n] = sum_pair sum_k A[m,k]*B[n,k], fp32 acc, 3-part bf16 split:
//   hi*hi + hi*lo + lo*hi  (error ~2^-16)
// BM=128, BN=128, BK=32; 4 warps (2x2), warp tile 64x64. 2 CTAs/SM.
#define BM 128
#define BN 128
#define NTHR 128
#define PITCHB 80                   // 32 bf16 + 8 pad  -> 80 bytes/row
#define PART_BYTES (128*PITCHB)     // 10240
#define STG_BYTES (4*PART_BYTES)    // 40960 (Ah, Al, Bh, Bl)
#define DSM_BYTES (2*STG_BYTES)     // 81920

struct BiasArr { const float* b[6]; };

// MODE 0: proj (z=job, bf split out, +bias), 1: scores (z=batch), 2: av (z=b|w<<4)
template<int MODE>
__global__ __launch_bounds__(NTHR, 2) void gemm_k(BiasArr ba) {
    const bf *Ah[2], *Al[2], *Bh[2], *Bl[2];
    float* Cf = nullptr; bf* Ch = nullptr; bf* Cl = nullptr;
    const float* bias = nullptr;
    size_t zoff = 0; int T = 32;
    if (MODE == 0) {
        const int job = blockIdx.z;
        Ah[0] = g_xh[job]; Al[0] = g_xl[job];
        Bh[0] = g_wh[job]; Bl[0] = g_wl[job];
        Ch = g_ph[job]; Cl = g_pl[job]; bias = ba.b[job];
        Ah[1] = Ah[0]; Al[1] = Al[0]; Bh[1] = Bh[0]; Bl[1] = Bl[0];
    } else if (MODE == 1) {
        zoff = (size_t)blockIdx.z * BATSTR;
        Ah[0] = g_ph[0]; Al[0] = g_pl[0]; Bh[0] = g_th[0]; Bl[0] = g_tl[0];
        Ah[1] = g_ph[1]; Al[1] = g_pl[1]; Bh[1] = g_ph[3]; Bl[1] = g_pl[3];
        Cf = g_att; T = 64;
    } else {
        const int b = blockIdx.z & 15, w = blockIdx.z >> 4;
        zoff = (size_t)b * BATSTR;
        Ah[0] = g_ah; Al[0] = g_al;
        Bh[0] = g_th[1 + w]; Bl[0] = g_tl[1 + w];
        Cf = w ? g_oi : g_or;
        Ah[1] = Ah[0]; Al[1] = Al[0]; Bh[1] = Bh[0]; Bl[1] = Bl[0];
    }
    const size_t zoffb = zoff * 2;                      // byte offset
    const int m0 = blockIdx.y * BM, n0 = blockIdx.x * BN;

    extern __shared__ char dsm[];
    const uint32_t base = smem_u32(dsm);
    const int tid = threadIdx.x, wid = tid >> 5, lane = tid & 31;
    const int wm = (wid >> 1) * 64;                     // 2 warp rows
    const int wn = (wid & 1) * 64;                      // 2 warp cols

    // cp.async mapping: each of 128 threads owns one 64B row per part (4 cp16)
    auto loads = [&](int it, int s) {
        const int pr = it >> 5;             // pair (scores only)
        const int kt = it & 31;             // k-tile within 1024
        const uint32_t sb = base + s * STG_BYTES;
        const size_t ga = zoffb + ((size_t)(m0 + tid) * 1024 + kt * 32) * 2;
        const size_t gb = zoffb + ((size_t)(n0 + tid) * 1024 + kt * 32) * 2;
        const uint32_t so = tid * PITCHB;
        const char* pAh = (const char*)Ah[pr] + ga;
        const char* pAl = (const char*)Al[pr] + ga;
        const char* pBh = (const char*)Bh[pr] + gb;
        const char* pBl = (const char*)Bl[pr] + gb;
        #pragma unroll
        for (int c = 0; c < 4; c++) {
            cp16(sb + so + c * 16,                 pAh + c * 16);
            cp16(sb + PART_BYTES + so + c * 16,    pAl + c * 16);
            cp16(sb + 2*PART_BYTES + so + c * 16,  pBh + c * 16);
            cp16(sb + 3*PART_BYTES + so + c * 16,  pBl + c * 16);
        }
    };

    // ldmatrix per-lane address components
    const int g = lane >> 3, lr = lane & 7;
    const uint32_t a_row = ((g & 1) * 8 + lr) * PITCHB;
    const uint32_t a_col = (g >> 1) * 16;
    const uint32_t b_row = ((g >> 1) * 8 + lr) * PITCHB;
    const uint32_t b_col = (g & 1) * 16;

    float acc[4][8][4] = {};

    loads(0, 0); CP_COMMIT();
    loads(1, 1); CP_COMMIT();

    for (int it = 0; it < T; ++it) {
        CP_WAIT1();
        __syncthreads();

        const uint32_t sb = base + (it & 1) * STG_BYTES;
        #pragma unroll
        for (int ks = 0; ks < 2; ++ks) {
            uint32_t bh4[4][4], bl4[4][4];
            const uint32_t ak = ks * 32 + a_col;
            const uint32_t bk = ks * 32 + b_col;
            #pragma unroll
            for (int nf2 = 0; nf2 < 4; ++nf2) {
                const uint32_t ro = (uint32_t)(wn + nf2 * 16) * PITCHB + b_row + bk;
                ldm4(bh4[nf2], sb + 2*PART_BYTES + ro);
                ldm4(bl4[nf2], sb + 3*PART_BYTES + ro);
            }
            #pragma unroll
            for (int mf = 0; mf < 4; ++mf) {
                uint32_t ah[4], al[4];
                const uint32_t ro = (uint32_t)(wm + mf * 16) * PITCHB + a_row + ak;
                ldm4(ah, sb + ro);
                ldm4(al, sb + PART_BYTES + ro);
                #pragma unroll
                for (int ni = 0; ni < 8; ++ni) {
                    const uint32_t* bh_f = &bh4[ni >> 1][(ni & 1) * 2];
                    const uint32_t* bl_f = &bl4[ni >> 1][(ni & 1) * 2];
                    mma16816(acc[mf][ni], ah, bh_f);   // hi*hi
                    mma16816(acc[mf][ni], ah, bl_f);   // hi*lo
                    mma16816(acc[mf][ni], al, bh_f);   // lo*hi
                }
            }
        }
        __syncthreads();
        if (it + 2 < T) loads(it + 2, it & 1);
        CP_COMMIT();
    }
    CP_WAIT0();

    // ---------------- epilogue (register -> gmem) ----------------
    const int em = m0 + wm + (lane >> 2);
    const int en = n0 + wn + (lane & 3) * 2;
    #pragma unroll
    for (int mi = 0; mi < 4; ++mi) {
        #pragma unroll
        for (int ni = 0; ni < 8; ++ni) {
            const int m = em + mi * 16;
            const int n = en + ni * 8;
            const float* a = acc[mi][ni];
            if (MODE != 0) {
                float2 v0 = {a[0], a[1]};
                float2 v1 = {a[2], a[3]};
                *(float2*)&Cf[zoff + (size_t)m * 1024 + n]       = v0;
                *(float2*)&Cf[zoff + (size_t)(m + 8) * 1024 + n] = v1;
            } else {
                const float b0 = __ldg(&bias[n]), b1 = __ldg(&bias[n + 1]);
                #pragma unroll
                for (int rr = 0; rr < 2; ++rr) {
                    const float v0 = a[rr * 2 + 0] + b0;
                    const float v1 = a[rr * 2 + 1] + b1;
                    bf h0 = __float2bfloat16_rn(v0), h1 = __float2bfloat16_rn(v1);
                    bf l0 = __float2bfloat16_rn(v0 - __bfloat162float(h0));
                    bf l1 = __float2bfloat16_rn(v1 - __bfloat162float(h1));
                    const size_t off = (size_t)(m + rr * 8) * 1024 + n;
                    __nv_bfloat162 t;
                    t.x = h0; t.y = h1; *(__nv_bfloat162*)(Ch + off) = t;
                    t.x = l0; t.y = l1; *(__nv_bfloat162*)(Cl + off) = t;
                }
            }
        }
    }
}

// ---------------- fp32 -> (hi, lo) bf16 split (merged, grid.y = tensor) -----
struct SplitArgs { const float4* src[6]; };

// MODE 0: weights (1M elems each) -> g_wh/g_wl ; MODE 1: inputs (16M) -> g_xh/g_xl
template<int MODE>
__global__ __launch_bounds__(256) void split6_k(SplitArgs sa) {
    const int job = blockIdx.y;
    bf* h = (MODE == 0) ? g_wh[job] : g_xh[job];
    bf* l = (MODE == 0) ? g_wl[job] : g_xl[job];
    const float4* src = sa.src[job];
    const int i = blockIdx.x * 256 + threadIdx.x;
    const float4 v = src[i];
    bf h0 = __float2bfloat16_rn(v.x), h1 = __float2bfloat16_rn(v.y);
    bf h2 = __float2bfloat16_rn(v.z), h3 = __float2bfloat16_rn(v.w);
    bf l0 = __float2bfloat16_rn(v.x - __bfloat162float(h0));
    bf l1 = __float2bfloat16_rn(v.y - __bfloat162float(h1));
    bf l2 = __float2bfloat16_rn(v.z - __bfloat162float(h2));
    bf l3 = __float2bfloat16_rn(v.w - __bfloat162float(h3));
    __nv_bfloat162 t;
    t.x = h0; t.y = h1; *(__nv_bfloat162*)(h + 4 * (size_t)i)     = t;
    t.x = h2; t.y = h3; *(__nv_bfloat162*)(h + 4 * (size_t)i + 2) = t;
    t.x = l0; t.y = l1; *(__nv_bfloat162*)(l + 4 * (size_t)i)     = t;
    t.x = l2; t.y = l3; *(__nv_bfloat162*)(l + 4 * (size_t)i + 2) = t;
}

// ---------------- batched 1024x1024 bf16 transpose (kr, vr, vi hi+lo) -------
__global__ __launch_bounds__(256) void transpose_k() {
    const int z = blockIdx.z, t = z >> 4, b = z & 15;
    const int si = (t == 0) ? 2 : (t == 1 ? 4 : 5);
    const bf* sh = g_ph[si] + (size_t)b * BATSTR;
    const bf* sl = g_pl[si] + (size_t)b * BATSTR;
    bf* dh = g_th[t] + (size_t)b * BATSTR;
    bf* dl = g_tl[t] + (size_t)b * BATSTR;
    __shared__ bf Th[32][33], Tl[32][33];
    const int tx = threadIdx.x, ty = threadIdx.y;
    const int x0 = blockIdx.x * 32, y0 = blockIdx.y * 32;
    #pragma unroll
    for (int j = ty; j < 32; j += 8) {
        Th[j][tx] = sh[(size_t)(y0 + j) * 1024 + x0 + tx];
        Tl[j][tx] = sl[(size_t)(y0 + j) * 1024 + x0 + tx];
    }
    __syncthreads();
    #pragma unroll
    for (int j = ty; j < 32; j += 8) {
        dh[(size_t)(x0 + j) * 1024 + y0 + tx] = Th[tx][j];
        dl[(size_t)(x0 + j) * 1024 + y0 + tx] = Tl[tx][j];
    }
}

// ---------------- softmax (scale 0.125 folded) -> split bf16 -----------------
__global__ __launch_bounds__(256) void softmax_k() {
    __shared__ float red[8];
    const size_t rowo = (size_t)blockIdx.x * 1024;
    const float* p = g_att + rowo;
    const int tid = threadIdx.x;

    float4 v = ((const float4*)p)[tid];
    v.x *= 0.125f; v.y *= 0.125f; v.z *= 0.125f; v.w *= 0.125f;

    float m = fmaxf(fmaxf(v.x, v.y), fmaxf(v.z, v.w));
    #pragma unroll
    for (int o = 16; o; o >>= 1) m = fmaxf(m, __shfl_xor_sync(0xffffffffu, m, o));
    if ((tid & 31) == 0) red[tid >> 5] = m;
    __syncthreads();
    float M = red[0];
    #pragma unroll
    for (int i = 1; i < 8; i++) M = fmaxf(M, red[i]);
    __syncthreads();

    v.x = expf(v.x - M); v.y = expf(v.y - M);
    v.z = expf(v.z - M); v.w = expf(v.w - M);
    float s = v.x + v.y + v.z + v.w;
    #pragma unroll
    for (int o = 16; o; o >>= 1) s += __shfl_xor_sync(0xffffffffu, s, o);
    if ((tid & 31) == 0) red[tid >> 5] = s;
    __syncthreads();
    float Tt = 0.f;
    #pragma unroll
    for (int i = 0; i < 8; i++) Tt += red[i];
    const float inv = 1.0f / Tt;
    v.x *= inv; v.y *= inv; v.z *= inv; v.w *= inv;

    bf h0 = __float2bfloat16_rn(v.x), h1 = __float2bfloat16_rn(v.y);
    bf h2 = __float2bfloat16_rn(v.z), h3 = __float2bfloat16_rn(v.w);
    bf l0 = __float2bfloat16_rn(v.x - __bfloat162float(h0));
    bf l1 = __float2bfloat16_rn(v.y - __bfloat162float(h1));
    bf l2 = __float2bfloat16_rn(v.z - __bfloat162float(h2));
    bf l3 = __float2bfloat16_rn(v.w - __bfloat162float(h3));
    const size_t o4 = rowo + (size_t)tid * 4;
    __nv_bfloat162 t;
    t.x = h0; t.y = h1; *(__nv_bfloat162*)(g_ah + o4)     = t;
    t.x = h2; t.y = h3; *(__nv_bfloat162*)(g_ah + o4 + 2) = t;
    t.x = l0; t.y = l1; *(__nv_bfloat162*)(g_al + o4)     = t;
    t.x = l2; t.y = l3; *(__nv_bfloat162*)(g_al + o4 + 2) = t;
}

// ---------------- complex LayerNorm + writeback ------------------------------
__global__ __launch_bounds__(256) void lnorm_k(const float* __restrict__ a2,
                                               const float* __restrict__ b2,
                                               float* __restrict__ out) {
    __shared__ float red[5][8];
    const size_t row = blockIdx.x;
    const int tid = threadIdx.x;
    const float4 ar = ((const float4*)(g_or + row * 1024))[tid];
    const float4 ai = ((const float4*)(g_oi + row * 1024))[tid];

    float sr  = ar.x + ar.y + ar.z + ar.w;
    float si  = ai.x + ai.y + ai.z + ai.w;
    float srr = ar.x*ar.x + ar.y*ar.y + ar.z*ar.z + ar.w*ar.w;
    float sii = ai.x*ai.x + ai.y*ai.y + ai.z*ai.z + ai.w*ai.w;
    float sri = ar.x*ai.x + ar.y*ai.y + ar.z*ai.z + ar.w*ai.w;
    #pragma unroll
    for (int o = 16; o; o >>= 1) {
        sr  += __shfl_xor_sync(0xffffffffu, sr,  o);
        si  += __shfl_xor_sync(0xffffffffu, si,  o);
        srr += __shfl_xor_sync(0xffffffffu, srr, o);
        sii += __shfl_xor_sync(0xffffffffu, sii, o);
        sri += __shfl_xor_sync(0xffffffffu, sri, o);
    }
    if ((tid & 31) == 0) {
        const int w = tid >> 5;
        red[0][w] = sr; red[1][w] = si; red[2][w] = srr;
        red[3][w] = sii; red[4][w] = sri;
    }
    __syncthreads();
    float Sr = 0, Si = 0, Srr = 0, Sii = 0, Sri = 0;
    #pragma unroll
    for (int i = 0; i < 8; i++) {
        Sr += red[0][i]; Si += red[1][i]; Srr += red[2][i];
        Sii += red[3][i]; Sri += red[4][i];
    }
    const float invD = 1.0f / 1024.0f;
    const float mr = Sr * invD, mi = Si * invD;
    const float vr = (Srr * invD - mr * mr) - (Sii * invD - mi * mi) + 1e-6f;
    const float vi = 2.0f * (Sri * invD - mr * mi);
    const float rad = sqrtf(vr * vr + vi * vi);
    const float c  = sqrtf(fmaxf(0.5f * (rad + vr), 0.0f));
    const float dd = copysignf(sqrtf(fmaxf(0.5f * (rad - vr), 0.0f)), vi);
    const float inv = 1.0f / (c * c + dd * dd);

    const int d0 = tid * 4;
    const float4 A2 = ((const float4*)a2)[tid];
    const float4 B2 = ((const float4*)b2)[tid];
    float4 yr, yi;
    { float wr = ar.x - mr, wi = ai.x - mi;
      yr.x = (wr*c + wi*dd)*inv*A2.x + B2.x; yi.x = (wi*c - wr*dd)*inv*A2.x; }
    { float wr = ar.y - mr, wi = ai.y - mi;
      yr.y = (wr*c + wi*dd)*inv*A2.y + B2.y; yi.y = (wi*c - wr*dd)*inv*A2.y; }
    { float wr = ar.z - mr, wi = ai.z - mi;
      yr.z = (wr*c + wi*dd)*inv*A2.z + B2.z; yi.z = (wi*c - wr*dd)*inv*A2.z; }
    { float wr = ar.w - mr, wi = ai.w - mi;
      yr.w = (wr*c + wi*dd)*inv*A2.w + B2.w; yi.w = (wi*c - wr*dd)*inv*A2.w; }
    *(float4*)&out[row * 1024 + d0] = yr;
    *(float4*)&out[(size_t)PLANE + row * 1024 + d0] = yi;
}

// ---------------------------------------------------------------------------
extern "C" void kernel_launch(void* const* d_in, const int* in_sizes, int n_in,
                              void* d_out, int out_size) {
    (void)in_sizes; (void)n_in; (void)out_size;
    cudaFuncSetAttribute(gemm_k<0>, cudaFuncAttributeMaxDynamicSharedMemorySize, DSM_BYTES);
    cudaFuncSetAttribute(gemm_k<1>, cudaFuncAttributeMaxDynamicSharedMemorySize, DSM_BYTES);
    cudaFuncSetAttribute(gemm_k<2>, cudaFuncAttributeMaxDynamicSharedMemorySize, DSM_BYTES);

    SplitArgs sw, sx;
    BiasArr ba, bz = {};
    for (int j = 0; j < 6; j++) {
        sx.src[j] = (const float4*)d_in[j];
        sw.src[j] = (const float4*)d_in[6 + 2 * j];
        ba.b[j]   = (const float*)d_in[7 + 2 * j];
    }
    // launch ordering: ncu profiles the 5th launch -> scores GEMM
    // 1: weights split (6 tensors)
    split6_k<0><<<dim3((DD_ * DD_) / 4 / 256, 6), 256>>>(sw);
    // 2: inputs split (6 tensors)
    split6_k<1><<<dim3(PLANE / 4 / 256, 6), 256>>>(sx);
    // 3: all 6 projections (X @ W^T + b) -> split bf16
    gemm_k<0><<<dim3(8, 128, 6), NTHR, DSM_BYTES>>>(ba);
    // 4: transpose kr, vr, vi (hi+lo) per batch
    transpose_k<<<dim3(32, 32, 48), dim3(32, 8)>>>();
    // 5: scores = qr@krT + qi@ki^T  (fp32)   <-- ncu target
    gemm_k<1><<<dim3(8, 8, 16), NTHR, DSM_BYTES>>>(bz);
    // 6: softmax (+0.125 scale) -> split bf16 attn
    softmax_k<<<MTOT, 256>>>();
    // 7: out_r = attn@vr AND out_i = attn@vi (merged, grid.z=32)
    gemm_k<2><<<dim3(8, 8, 32), NTHR, DSM_BYTES>>>(bz);
    // 8: complex LayerNorm -> [2,B,S,D]
    lnorm_k<<<MTOT, 256>>>((const float*)d_in[18], (const float*)d_in[19], (float*)d_out);
}

// round 8
// speedup vs baseline: 1.1342x; 1.1342x over previous
#include <cuda_runtime.h>
#include <cuda_bf16.h>
#include <cstdint>

typedef __nv_bfloat16 bf;

#define NB 16
#define SS_ 1024
#define DD_ 1024
#define MTOT (NB*SS_)              // 16384
#define PLANE (MTOT*DD_)           // 16,777,216
#define BATSTR (SS_*DD_)           // 1,048,576

// ---------------- device scratch (statics; no allocation allowed) ----------
__device__ bf g_xh[6][PLANE];      __device__ bf g_xl[6][PLANE];      // split inputs
__device__ bf g_wh[6][DD_*DD_];    __device__ bf g_wl[6][DD_*DD_];    // split weights
__device__ bf g_ph[6][PLANE];      __device__ bf g_pl[6][PLANE];      // proj outputs
__device__ bf g_th[3][PLANE];      __device__ bf g_tl[3][PLANE];      // transposed kr,vr,vi
__device__ bf g_ah[PLANE];         __device__ bf g_al[PLANE];         // split attn
__device__ float g_att[PLANE];     // raw scores
__device__ float g_or[PLANE];      __device__ float g_oi[PLANE];

// ---------------- helpers ---------------------------------------------------
__device__ __forceinline__ uint32_t smem_u32(const void* p) {
    uint32_t a;
    asm("{ .reg .u64 t; cvta.to.shared.u64 t, %1; cvt.u32.u64 %0, t; }"
        : "=r"(a) : "l"(p));
    return a;
}
__device__ __forceinline__ void cp16(uint32_t s, const void* g) {
    asm volatile("cp.async.cg.shared.global [%0], [%1], 16;" :: "r"(s), "l"(g));
}
#define CP_COMMIT() asm volatile("cp.async.commit_group;" ::: "memory")
#define CP_WAIT1()  asm volatile("cp.async.wait_group 1;" ::: "memory")
#define CP_WAIT0()  asm volatile("cp.async.wait_group 0;" ::: "memory")

__device__ __forceinline__ void ldm4(uint32_t* r, uint32_t addr) {
    asm volatile("ldmatrix.sync.aligned.m8n8.x4.shared.b16 {%0,%1,%2,%3}, [%4];"
        : "=r"(r[0]), "=r"(r[1]), "=r"(r[2]), "=r"(r[3]) : "r"(addr));
}
__device__ __forceinline__ void mma16816(float* d, const uint32_t* a, const uint32_t* b) {
    asm volatile(
        "mma.sync.aligned.m16n8k16.row.col.f32.bf16.bf16.f32 "
        "{%0,%1,%2,%3}, {%4,%5,%6,%7}, {%8,%9}, {%0,%1,%2,%3};"
        : "+f"(d[0]), "+f"(d[1]), "+f"(d[2]), "+f"(d[3])
        : "r"(a[0]), "r"(a[1]), "r"(a[2]), "r"(a[3]), "r"(b[0]), "r"(b[1]));
}

// ---------------- tensor-core split-bf16 NT GEMM ----------------------------
// C[m,n] = sum_pair sum_k A[m,k]*B[n,k], fp32 acc, 3-part bf16 split:
//   hi*hi + hi*lo + lo*hi  (error ~2^-16)
// BM=128, BN=128, BK=32; 8 warps (2x4), warp tile 64x32. 2 CTAs/SM.
#define BM 128
#define BN 128
#define PITCHB 80                   // 32 bf16 + 8 pad  -> 80 bytes/row
#define PART_BYTES (128*PITCHB)     // 10240
#define STG_BYTES (4*PART_BYTES)    // 40960 (Ah, Al, Bh, Bl)
#define DSM_BYTES (2*STG_BYTES)     // 81920

struct BiasArr { const float* b[6]; };

// MODE 0: proj (z=job, bf split out, +bias), 1: scores (z=batch), 2: av (z=b|w<<4)
template<int MODE>
__global__ __launch_bounds__(256, 2) void gemm_k(BiasArr ba) {
    const bf *Ah[2], *Al[2], *Bh[2], *Bl[2];
    float* Cf = nullptr; bf* Ch = nullptr; bf* Cl = nullptr;
    const float* bias = nullptr;
    size_t zoff = 0; int T = 32;
    if (MODE == 0) {
        const int job = blockIdx.z;
        Ah[0] = g_xh[job]; Al[0] = g_xl[job];
        Bh[0] = g_wh[job]; Bl[0] = g_wl[job];
        Ch = g_ph[job]; Cl = g_pl[job]; bias = ba.b[job];
        Ah[1] = Ah[0]; Al[1] = Al[0]; Bh[1] = Bh[0]; Bl[1] = Bl[0];
    } else if (MODE == 1) {
        zoff = (size_t)blockIdx.z * BATSTR;
        Ah[0] = g_ph[0]; Al[0] = g_pl[0]; Bh[0] = g_th[0]; Bl[0] = g_tl[0];
        Ah[1] = g_ph[1]; Al[1] = g_pl[1]; Bh[1] = g_ph[3]; Bl[1] = g_pl[3];
        Cf = g_att; T = 64;
    } else {
        const int b = blockIdx.z & 15, w = blockIdx.z >> 4;
        zoff = (size_t)b * BATSTR;
        Ah[0] = g_ah; Al[0] = g_al;
        Bh[0] = g_th[1 + w]; Bl[0] = g_tl[1 + w];
        Cf = w ? g_oi : g_or;
        Ah[1] = Ah[0]; Al[1] = Al[0]; Bh[1] = Bh[0]; Bl[1] = Bl[0];
    }
    const size_t zoffb = zoff * 2;                      // byte offset
    const int m0 = blockIdx.y * BM, n0 = blockIdx.x * BN;

    extern __shared__ char dsm[];
    const uint32_t base = smem_u32(dsm);
    const int tid = threadIdx.x, wid = tid >> 5, lane = tid & 31;
    const int wm = (wid >> 2) * 64;                     // warp m-offset
    const int wn = (wid & 3) * 32;                      // warp n-offset

    // cp.async mapping: each thread owns 2 consecutive 16B chunks per part
    const int ld_row = tid >> 1;            // 0..127
    const int ld_col = (tid & 1) * 2;       // chunk 0/2

    auto loads = [&](int it, int s) {
        const int pr = it >> 5;             // pair (scores only)
        const int kt = it & 31;             // k-tile within 1024
        const uint32_t sb = base + s * STG_BYTES;
        const size_t ga = zoffb + ((size_t)(m0 + ld_row) * 1024 + kt * 32) * 2 + ld_col * 16;
        const size_t gb = zoffb + ((size_t)(n0 + ld_row) * 1024 + kt * 32) * 2 + ld_col * 16;
        const uint32_t so = ld_row * PITCHB + ld_col * 16;
        const char* pAh = (const char*)Ah[pr] + ga;
        const char* pAl = (const char*)Al[pr] + ga;
        const char* pBh = (const char*)Bh[pr] + gb;
        const char* pBl = (const char*)Bl[pr] + gb;
        cp16(sb + so,                     pAh);
        cp16(sb + so + 16,                pAh + 16);
        cp16(sb + PART_BYTES + so,        pAl);
        cp16(sb + PART_BYTES + so + 16,   pAl + 16);
        cp16(sb + 2*PART_BYTES + so,      pBh);
        cp16(sb + 2*PART_BYTES + so + 16, pBh + 16);
        cp16(sb + 3*PART_BYTES + so,      pBl);
        cp16(sb + 3*PART_BYTES + so + 16, pBl + 16);
    };

    // ldmatrix per-lane address components
    const int g = lane >> 3, lr = lane & 7;
    const uint32_t a_row = ((g & 1) * 8 + lr) * PITCHB;
    const uint32_t a_col = (g >> 1) * 16;
    const uint32_t b_row = ((g >> 1) * 8 + lr) * PITCHB;
    const uint32_t b_col = (g & 1) * 16;

    float acc[4][4][4] = {};

    loads(0, 0); CP_COMMIT();
    loads(1, 1); CP_COMMIT();

    for (int it = 0; it < T; ++it) {
        CP_WAIT1();
        __syncthreads();

        const uint32_t sb = base + (it & 1) * STG_BYTES;
        #pragma unroll
        for (int ks = 0; ks < 2; ++ks) {
            uint32_t bh4[2][4], bl4[2][4];
            const uint32_t ak = ks * 32 + a_col;
            const uint32_t bk = ks * 32 + b_col;
            #pragma unroll
            for (int nf2 = 0; nf2 < 2; ++nf2) {
                const uint32_t ro = (uint32_t)(wn + nf2 * 16) * PITCHB + b_row + bk;
                ldm4(bh4[nf2], sb + 2*PART_BYTES + ro);
                ldm4(bl4[nf2], sb + 3*PART_BYTES + ro);
            }
            #pragma unroll
            for (int mf = 0; mf < 4; ++mf) {
                uint32_t ah[4], al[4];
                const uint32_t ro = (uint32_t)(wm + mf * 16) * PITCHB + a_row + ak;
                ldm4(ah, sb + ro);
                ldm4(al, sb + PART_BYTES + ro);
                // grouped by split-term: RAW chain on each acc spaced 4 MMAs apart
                #pragma unroll
                for (int ni = 0; ni < 4; ++ni)
                    mma16816(acc[mf][ni], ah, &bh4[ni >> 1][(ni & 1) * 2]);   // hi*hi
                #pragma unroll
                for (int ni = 0; ni < 4; ++ni)
                    mma16816(acc[mf][ni], ah, &bl4[ni >> 1][(ni & 1) * 2]);   // hi*lo
                #pragma unroll
                for (int ni = 0; ni < 4; ++ni)
                    mma16816(acc[mf][ni], al, &bh4[ni >> 1][(ni & 1) * 2]);   // lo*hi
            }
        }
        __syncthreads();
        if (it + 2 < T) loads(it + 2, it & 1);
        CP_COMMIT();
    }
    CP_WAIT0();

    // ---------------- epilogue (register -> gmem) ----------------
    const int em = m0 + wm + (lane >> 2);
    const int en = n0 + wn + (lane & 3) * 2;
    #pragma unroll
    for (int mi = 0; mi < 4; ++mi) {
        #pragma unroll
        for (int ni = 0; ni < 4; ++ni) {
            const int m = em + mi * 16;
            const int n = en + ni * 8;
            const float* a = acc[mi][ni];
            if (MODE != 0) {
                float2 v0 = {a[0], a[1]};
                float2 v1 = {a[2], a[3]};
                *(float2*)&Cf[zoff + (size_t)m * 1024 + n]       = v0;
                *(float2*)&Cf[zoff + (size_t)(m + 8) * 1024 + n] = v1;
            } else {
                const float b0 = __ldg(&bias[n]), b1 = __ldg(&bias[n + 1]);
                #pragma unroll
                for (int rr = 0; rr < 2; ++rr) {
                    const float v0 = a[rr * 2 + 0] + b0;
                    const float v1 = a[rr * 2 + 1] + b1;
                    bf h0 = __float2bfloat16_rn(v0), h1 = __float2bfloat16_rn(v1);
                    bf l0 = __float2bfloat16_rn(v0 - __bfloat162float(h0));
                    bf l1 = __float2bfloat16_rn(v1 - __bfloat162float(h1));
                    const size_t off = (size_t)(m + rr * 8) * 1024 + n;
                    __nv_bfloat162 t;
                    t.x = h0; t.y = h1; *(__nv_bfloat162*)(Ch + off) = t;
                    t.x = l0; t.y = l1; *(__nv_bfloat162*)(Cl + off) = t;
                }
            }
        }
    }
}

// ---------------- fp32 -> (hi, lo) bf16 split (12 jobs in one launch) -------
struct SplitArgs12 { const float4* src[12]; };   // 0-5 inputs, 6-11 weights

__global__ __launch_bounds__(256) void split12_k(SplitArgs12 sa) {
    const int job = blockIdx.y;
    const bool isw = job >= 6;
    const int n4 = isw ? (DD_ * DD_ / 4) : (PLANE / 4);
    const int i = blockIdx.x * 256 + threadIdx.x;
    if (i >= n4) return;
    bf* h = isw ? g_wh[job - 6] : g_xh[job];
    bf* l = isw ? g_wl[job - 6] : g_xl[job];
    const float4 v = sa.src[job][i];
    bf h0 = __float2bfloat16_rn(v.x), h1 = __float2bfloat16_rn(v.y);
    bf h2 = __float2bfloat16_rn(v.z), h3 = __float2bfloat16_rn(v.w);
    bf l0 = __float2bfloat16_rn(v.x - __bfloat162float(h0));
    bf l1 = __float2bfloat16_rn(v.y - __bfloat162float(h1));
    bf l2 = __float2bfloat16_rn(v.z - __bfloat162float(h2));
    bf l3 = __float2bfloat16_rn(v.w - __bfloat162float(h3));
    __nv_bfloat162 t;
    t.x = h0; t.y = h1; *(__nv_bfloat162*)(h + 4 * (size_t)i)     = t;
    t.x = h2; t.y = h3; *(__nv_bfloat162*)(h + 4 * (size_t)i + 2) = t;
    t.x = l0; t.y = l1; *(__nv_bfloat162*)(l + 4 * (size_t)i)     = t;
    t.x = l2; t.y = l3; *(__nv_bfloat162*)(l + 4 * (size_t)i + 2) = t;
}

// ---------------- batched 1024x1024 bf16 transpose (kr, vr, vi hi+lo) -------
__global__ __launch_bounds__(256) void transpose_k() {
    const int z = blockIdx.z, t = z >> 4, b = z & 15;
    const int si = (t == 0) ? 2 : (t == 1 ? 4 : 5);
    const bf* sh = g_ph[si] + (size_t)b * BATSTR;
    const bf* sl = g_pl[si] + (size_t)b * BATSTR;
    bf* dh = g_th[t] + (size_t)b * BATSTR;
    bf* dl = g_tl[t] + (size_t)b * BATSTR;
    __shared__ bf Th[32][33], Tl[32][33];
    const int tx = threadIdx.x, ty = threadIdx.y;
    const int x0 = blockIdx.x * 32, y0 = blockIdx.y * 32;
    #pragma unroll
    for (int j = ty; j < 32; j += 8) {
        Th[j][tx] = sh[(size_t)(y0 + j) * 1024 + x0 + tx];
        Tl[j][tx] = sl[(size_t)(y0 + j) * 1024 + x0 + tx];
    }
    __syncthreads();
    #pragma unroll
    for (int j = ty; j < 32; j += 8) {
        dh[(size_t)(x0 + j) * 1024 + y0 + tx] = Th[tx][j];
        dl[(size_t)(x0 + j) * 1024 + y0 + tx] = Tl[tx][j];
    }
}

// ---------------- softmax (scale 0.125 folded) -> split bf16 -----------------
__global__ __launch_bounds__(256) void softmax_k() {
    __shared__ float red[8];
    const size_t rowo = (size_t)blockIdx.x * 1024;
    const float* p = g_att + rowo;
    const int tid = threadIdx.x;

    float4 v = ((const float4*)p)[tid];
    v.x *= 0.125f; v.y *= 0.125f; v.z *= 0.125f; v.w *= 0.125f;

    float m = fmaxf(fmaxf(v.x, v.y), fmaxf(v.z, v.w));
    #pragma unroll
    for (int o = 16; o; o >>= 1) m = fmaxf(m, __shfl_xor_sync(0xffffffffu, m, o));
    if ((tid & 31) == 0) red[tid >> 5] = m;
    __syncthreads();
    float M = red[0];
    #pragma unroll
    for (int i = 1; i < 8; i++) M = fmaxf(M, red[i]);
    __syncthreads();

    v.x = __expf(v.x - M); v.y = __expf(v.y - M);
    v.z = __expf(v.z - M); v.w = __expf(v.w - M);
    float s = v.x + v.y + v.z + v.w;
    #pragma unroll
    for (int o = 16; o; o >>= 1) s += __shfl_xor_sync(0xffffffffu, s, o);
    if ((tid & 31) == 0) red[tid >> 5] = s;
    __syncthreads();
    float Tt = 0.f;
    #pragma unroll
    for (int i = 0; i < 8; i++) Tt += red[i];
    const float inv = 1.0f / Tt;
    v.x *= inv; v.y *= inv; v.z *= inv; v.w *= inv;

    bf h0 = __float2bfloat16_rn(v.x), h1 = __float2bfloat16_rn(v.y);
    bf h2 = __float2bfloat16_rn(v.z), h3 = __float2bfloat16_rn(v.w);
    bf l0 = __float2bfloat16_rn(v.x - __bfloat162float(h0));
    bf l1 = __float2bfloat16_rn(v.y - __bfloat162float(h1));
    bf l2 = __float2bfloat16_rn(v.z - __bfloat162float(h2));
    bf l3 = __float2bfloat16_rn(v.w - __bfloat162float(h3));
    const size_t o4 = rowo + (size_t)tid * 4;
    __nv_bfloat162 t;
    t.x = h0; t.y = h1; *(__nv_bfloat162*)(g_ah + o4)     = t;
    t.x = h2; t.y = h3; *(__nv_bfloat162*)(g_ah + o4 + 2) = t;
    t.x = l0; t.y = l1; *(__nv_bfloat162*)(g_al + o4)     = t;
    t.x = l2; t.y = l3; *(__nv_bfloat162*)(g_al + o4 + 2) = t;
}

// ---------------- complex LayerNorm + writeback ------------------------------
__global__ __launch_bounds__(256) void lnorm_k(const float* __restrict__ a2,
                                               const float* __restrict__ b2,
                                               float* __restrict__ out) {
    __shared__ float red[5][8];
    const size_t row = blockIdx.x;
    const int tid = threadIdx.x;
    const float4 ar = ((const float4*)(g_or + row * 1024))[tid];
    const float4 ai = ((const float4*)(g_oi + row * 1024))[tid];

    float sr  = ar.x + ar.y + ar.z + ar.w;
    float si  = ai.x + ai.y + ai.z + ai.w;
    float srr = ar.x*ar.x + ar.y*ar.y + ar.z*ar.z + ar.w*ar.w;
    float sii = ai.x*ai.x + ai.y*ai.y + ai.z*ai.z + ai.w*ai.w;
    float sri = ar.x*ai.x + ar.y*ai.y + ar.z*ai.z + ar.w*ai.w;
    #pragma unroll
    for (int o = 16; o; o >>= 1) {
        sr  += __shfl_xor_sync(0xffffffffu, sr,  o);
        si  += __shfl_xor_sync(0xffffffffu, si,  o);
        srr += __shfl_xor_sync(0xffffffffu, srr, o);
        sii += __shfl_xor_sync(0xffffffffu, sii, o);
        sri += __shfl_xor_sync(0xffffffffu, sri, o);
    }
    if ((tid & 31) == 0) {
        const int w = tid >> 5;
        red[0][w] = sr; red[1][w] = si; red[2][w] = srr;
        red[3][w] = sii; red[4][w] = sri;
    }
    __syncthreads();
    float Sr = 0, Si = 0, Srr = 0, Sii = 0, Sri = 0;
    #pragma unroll
    for (int i = 0; i < 8; i++) {
        Sr += red[0][i]; Si += red[1][i]; Srr += red[2][i];
        Sii += red[3][i]; Sri += red[4][i];
    }
    const float invD = 1.0f / 1024.0f;
    const float mr = Sr * invD, mi = Si * invD;
    const float vr = (Srr * invD - mr * mr) - (Sii * invD - mi * mi) + 1e-6f;
    const float vi = 2.0f * (Sri * invD - mr * mi);
    const float rad = sqrtf(vr * vr + vi * vi);
    const float c  = sqrtf(fmaxf(0.5f * (rad + vr), 0.0f));
    const float dd = copysignf(sqrtf(fmaxf(0.5f * (rad - vr), 0.0f)), vi);
    const float inv = 1.0f / (c * c + dd * dd);

    const int d0 = tid * 4;
    const float4 A2 = ((const float4*)a2)[tid];
    const float4 B2 = ((const float4*)b2)[tid];
    float4 yr, yi;
    { float wr = ar.x - mr, wi = ai.x - mi;
      yr.x = (wr*c + wi*dd)*inv*A2.x + B2.x; yi.x = (wi*c - wr*dd)*inv*A2.x; }
    { float wr = ar.y - mr, wi = ai.y - mi;
      yr.y = (wr*c + wi*dd)*inv*A2.y + B2.y; yi.y = (wi*c - wr*dd)*inv*A2.y; }
    { float wr = ar.z - mr, wi = ai.z - mi;
      yr.z = (wr*c + wi*dd)*inv*A2.z + B2.z; yi.z = (wi*c - wr*dd)*inv*A2.z; }
    { float wr = ar.w - mr, wi = ai.w - mi;
      yr.w = (wr*c + wi*dd)*inv*A2.w + B2.w; yi.w = (wi*c - wr*dd)*inv*A2.w; }
    *(float4*)&out[row * 1024 + d0] = yr;
    *(float4*)&out[(size_t)PLANE + row * 1024 + d0] = yi;
}

// ---------------------------------------------------------------------------
extern "C" void kernel_launch(void* const* d_in, const int* in_sizes, int n_in,
                              void* d_out, int out_size) {
    (void)in_sizes; (void)n_in; (void)out_size;
    cudaFuncSetAttribute(gemm_k<0>, cudaFuncAttributeMaxDynamicSharedMemorySize, DSM_BYTES);
    cudaFuncSetAttribute(gemm_k<1>, cudaFuncAttributeMaxDynamicSharedMemorySize, DSM_BYTES);
    cudaFuncSetAttribute(gemm_k<2>, cudaFuncAttributeMaxDynamicSharedMemorySize, DSM_BYTES);

    SplitArgs12 sp;
    BiasArr ba, bz = {};
    for (int j = 0; j < 6; j++) {
        sp.src[j]     = (const float4*)d_in[j];           // inputs
        sp.src[6 + j] = (const float4*)d_in[6 + 2 * j];   // weights
        ba.b[j]       = (const float*)d_in[7 + 2 * j];
    }
    // ncu empirically captures launch #4 -> scores GEMM
    // 1: all 12 splits (inputs + weights)
    split12_k<<<dim3(PLANE / 4 / 256, 12), 256>>>(sp);
    // 2: all 6 projections (X @ W^T + b) -> split bf16
    gemm_k<0><<<dim3(8, 128, 6), 256, DSM_BYTES>>>(ba);
    // 3: transpose kr, vr, vi (hi+lo) per batch
    transpose_k<<<dim3(32, 32, 48), dim3(32, 8)>>>();
    // 4: scores = qr@krT + qi@ki^T  (fp32)   <-- ncu target
    gemm_k<1><<<dim3(8, 8, 16), 256, DSM_BYTES>>>(bz);
    // 5: softmax (+0.125 scale) -> split bf16 attn
    softmax_k<<<MTOT, 256>>>();
    // 6: out_r = attn@vr AND out_i = attn@vi (merged, grid.z=32)
    gemm_k<2><<<dim3(8, 8, 32), 256, DSM_BYTES>>>(bz);
    // 7: complex LayerNorm -> [2,B,S,D]
    lnorm_k<<<MTOT, 256>>>((const float*)d_in[18], (const float*)d_in[19], (float*)d_out);
}

// round 11
// speedup vs baseline: 1.2378x; 1.0913x over previous
#include <cuda_runtime.h>
#include <cuda_bf16.h>
#include <cstdint>

typedef __nv_bfloat16 bf;

#define NB 16
#define SS_ 1024
#define DD_ 1024
#define MTOT (NB*SS_)              // 16384
#define PLANE (MTOT*DD_)           // 16,777,216
#define BATSTR (SS_*DD_)           // 1,048,576

// ---------------- device scratch (statics; no allocation allowed) ----------
__device__ bf g_xh[6][PLANE];      __device__ bf g_xl[6][PLANE];      // split inputs
__device__ bf g_wh[6][DD_*DD_];    __device__ bf g_wl[6][DD_*DD_];    // split weights
__device__ bf g_ph[6][PLANE];      __device__ bf g_pl[6][PLANE];      // proj outputs
__device__ bf g_th[3][PLANE];      __device__ bf g_tl[3][PLANE];      // transposed kr,vr,vi
__device__ bf g_ah[PLANE];         __device__ bf g_al[PLANE];         // split attn
__device__ float g_att[PLANE];     // raw scores
__device__ float g_or[PLANE];      __device__ float g_oi[PLANE];

// ---------------- helpers ---------------------------------------------------
__device__ __forceinline__ uint32_t smem_u32(const void* p) {
    uint32_t a;
    asm("{ .reg .u64 t; cvta.to.shared.u64 t, %1; cvt.u32.u64 %0, t; }"
        : "=r"(a) : "l"(p));
    return a;
}
__device__ __forceinline__ void cp16(uint32_t s, const void* g) {
    asm volatile("cp.async.cg.shared.global [%0], [%1], 16;" :: "r"(s), "l"(g));
}
#define CP_COMMIT() asm volatile("cp.async.commit_group;" ::: "memory")
#define CP_WAIT1()  asm volatile("cp.async.wait_group 1;" ::: "memory")
#define CP_WAIT0()  asm volatile("cp.async.wait_group 0;" ::: "memory")

__device__ __forceinline__ void ldm4(uint32_t* r, uint32_t addr) {
    asm volatile("ldmatrix.sync.aligned.m8n8.x4.shared.b16 {%0,%1,%2,%3}, [%4];"
        : "=r"(r[0]), "=r"(r[1]), "=r"(r[2]), "=r"(r[3]) : "r"(addr));
}
__device__ __forceinline__ void mma16816(float* d, const uint32_t* a, const uint32_t* b) {
    asm volatile(
        "mma.sync.aligned.m16n8k16.row.col.f32.bf16.bf16.f32 "
        "{%0,%1,%2,%3}, {%4,%5,%6,%7}, {%8,%9}, {%0,%1,%2,%3};"
        : "+f"(d[0]), "+f"(d[1]), "+f"(d[2]), "+f"(d[3])
        : "r"(a[0]), "r"(a[1]), "r"(a[2]), "r"(a[3]), "r"(b[0]), "r"(b[1]));
}

// ---------------- tensor-core split-bf16 NT GEMM ----------------------------
// C[m,n] = sum_pair sum_k A[m,k]*B[n,k], fp32 acc, 3-part bf16 split:
//   hi*hi + hi*lo + lo*hi  (error ~2^-16)
// BM=128, BN=128, BK=32; 8 warps (2x4), warp tile 64x32. 2 CTAs/SM.
// Packed rows: [64B hi | 64B lo | 16B pad] -> pitch 144, conflict-free
// (144 mod 128 = 16 -> 8 distinct banks per ldmatrix). 3 stages, 1 sync/iter.
#define BM 128
#define BN 128
#define PITCH 144
#define PACK_BYTES (128*PITCH)      // 18432 (one operand: hi+lo)
#define OFF_B PACK_BYTES            // B pack offset within stage
#define STG_BYTES (2*PACK_BYTES)    // 36864
#define DSM_BYTES (3*STG_BYTES)     // 110592  (x2 CTAs = 221184 <= 228KB)

struct BiasArr { const float* b[6]; };

// MODE 0: proj (z=job, bf split out, +bias), 1: scores (z=batch), 2: av (z=b|w<<4)
template<int MODE>
__global__ __launch_bounds__(256, 2) void gemm_k(BiasArr ba) {
    const bf *Ah[2], *Al[2], *Bh[2], *Bl[2];
    float* Cf = nullptr; bf* Ch = nullptr; bf* Cl = nullptr;
    const float* bias = nullptr;
    size_t zoff = 0; int T = 32;
    if (MODE == 0) {
        const int job = blockIdx.z;
        Ah[0] = g_xh[job]; Al[0] = g_xl[job];
        Bh[0] = g_wh[job]; Bl[0] = g_wl[job];
        Ch = g_ph[job]; Cl = g_pl[job]; bias = ba.b[job];
        Ah[1] = Ah[0]; Al[1] = Al[0]; Bh[1] = Bh[0]; Bl[1] = Bl[0];
    } else if (MODE == 1) {
        zoff = (size_t)blockIdx.z * BATSTR;
        Ah[0] = g_ph[0]; Al[0] = g_pl[0]; Bh[0] = g_th[0]; Bl[0] = g_tl[0];
        Ah[1] = g_ph[1]; Al[1] = g_pl[1]; Bh[1] = g_ph[3]; Bl[1] = g_pl[3];
        Cf = g_att; T = 64;
    } else {
        const int b = blockIdx.z & 15, w = blockIdx.z >> 4;
        zoff = (size_t)b * BATSTR;
        Ah[0] = g_ah; Al[0] = g_al;
        Bh[0] = g_th[1 + w]; Bl[0] = g_tl[1 + w];
        Cf = w ? g_oi : g_or;
        Ah[1] = Ah[0]; Al[1] = Al[0]; Bh[1] = Bh[0]; Bl[1] = Bl[0];
    }
    const size_t zoffb = zoff * 2;                      // byte offset
    const int m0 = blockIdx.y * BM, n0 = blockIdx.x * BN;

    extern __shared__ char dsm[];
    const uint32_t base = smem_u32(dsm);
    const int tid = threadIdx.x, wid = tid >> 5, lane = tid & 31;
    const int wm = (wid >> 2) * 64;                     // warp m-offset
    const int wn = (wid & 3) * 32;                      // warp n-offset

    // loader: thread -> row (tid>>1), 32B half (tid&1) of each 64B part-row
    const int ld_row = tid >> 1;
    const uint32_t ld_half = (tid & 1) * 32;

    auto loads = [&](int it, int s) {
        const int pr = it >> 5;             // pair (scores only)
        const int kt = it & 31;             // k-tile within 1024
        const uint32_t sb = base + s * STG_BYTES;
        const size_t ga = zoffb + ((size_t)(m0 + ld_row) * 1024 + kt * 32) * 2 + ld_half;
        const size_t gb = zoffb + ((size_t)(n0 + ld_row) * 1024 + kt * 32) * 2 + ld_half;
        const uint32_t so = ld_row * PITCH + ld_half;
        const char* pAh = (const char*)Ah[pr] + ga;
        const char* pAl = (const char*)Al[pr] + ga;
        const char* pBh = (const char*)Bh[pr] + gb;
        const char* pBl = (const char*)Bl[pr] + gb;
        cp16(sb + so,                pAh);
        cp16(sb + so + 16,           pAh + 16);
        cp16(sb + so + 64,           pAl);
        cp16(sb + so + 64 + 16,      pAl + 16);
        cp16(sb + OFF_B + so,        pBh);
        cp16(sb + OFF_B + so + 16,   pBh + 16);
        cp16(sb + OFF_B + so + 64,   pBl);
        cp16(sb + OFF_B + so + 64 + 16, pBl + 16);
    };

    // ldmatrix per-lane address components
    const int g = lane >> 3, lr = lane & 7;
    const uint32_t a_row = ((g & 1) * 8 + lr) * PITCH;
    const uint32_t a_col = (g >> 1) * 16;
    const uint32_t b_row = ((g >> 1) * 8 + lr) * PITCH;
    const uint32_t b_col = (g & 1) * 16;

    float acc[4][4][4] = {};

    loads(0, 0); CP_COMMIT();
    loads(1, 1); CP_COMMIT();

    int cs = 0, ls = 2;                    // compute stage, load stage
    for (int it = 0; it < T; ++it) {
        CP_WAIT1();                        // stage cs arrived
        __syncthreads();                   // all warps done with stage ls (read 2 iters ago)
        if (it + 2 < T) loads(it + 2, ls);
        CP_COMMIT();

        const uint32_t sb = base + cs * STG_BYTES;
        #pragma unroll
        for (int ks = 0; ks < 2; ++ks) {
            uint32_t bh4[2][4], bl4[2][4];
            const uint32_t ak = ks * 32 + a_col;
            const uint32_t bk = ks * 32 + b_col;
            #pragma unroll
            for (int nf2 = 0; nf2 < 2; ++nf2) {
                const uint32_t ro = OFF_B + (uint32_t)(wn + nf2 * 16) * PITCH + b_row + bk;
                ldm4(bh4[nf2], sb + ro);
                ldm4(bl4[nf2], sb + ro + 64);
            }
            #pragma unroll
            for (int mf = 0; mf < 4; ++mf) {
                uint32_t ah[4], al[4];
                const uint32_t ro = (uint32_t)(wm + mf * 16) * PITCH + a_row + ak;
                ldm4(ah, sb + ro);
                ldm4(al, sb + ro + 64);
                #pragma unroll
                for (int ni = 0; ni < 4; ++ni) {
                    const uint32_t* bh_f = &bh4[ni >> 1][(ni & 1) * 2];
                    const uint32_t* bl_f = &bl4[ni >> 1][(ni & 1) * 2];
                    mma16816(acc[mf][ni], ah, bh_f);   // hi*hi
                    mma16816(acc[mf][ni], ah, bl_f);   // hi*lo
                    mma16816(acc[mf][ni], al, bh_f);   // lo*hi
                }
            }
        }
        cs = (cs == 2) ? 0 : cs + 1;
        ls = (ls == 2) ? 0 : ls + 1;
    }
    CP_WAIT0();

    // ---------------- epilogue (register -> gmem) ----------------
    const int em = m0 + wm + (lane >> 2);
    const int en = n0 + wn + (lane & 3) * 2;
    #pragma unroll
    for (int mi = 0; mi < 4; ++mi) {
        #pragma unroll
        for (int ni = 0; ni < 4; ++ni) {
            const int m = em + mi * 16;
            const int n = en + ni * 8;
            const float* a = acc[mi][ni];
            if (MODE != 0) {
                float2 v0 = {a[0], a[1]};
                float2 v1 = {a[2], a[3]};
                *(float2*)&Cf[zoff + (size_t)m * 1024 + n]       = v0;
                *(float2*)&Cf[zoff + (size_t)(m + 8) * 1024 + n] = v1;
            } else {
                const float b0 = __ldg(&bias[n]), b1 = __ldg(&bias[n + 1]);
                #pragma unroll
                for (int rr = 0; rr < 2; ++rr) {
                    const float v0 = a[rr * 2 + 0] + b0;
                    const float v1 = a[rr * 2 + 1] + b1;
                    bf h0 = __float2bfloat16_rn(v0), h1 = __float2bfloat16_rn(v1);
                    bf l0 = __float2bfloat16_rn(v0 - __bfloat162float(h0));
                    bf l1 = __float2bfloat16_rn(v1 - __bfloat162float(h1));
                    const size_t off = (size_t)(m + rr * 8) * 1024 + n;
                    __nv_bfloat162 t;
                    t.x = h0; t.y = h1; *(__nv_bfloat162*)(Ch + off) = t;
                    t.x = l0; t.y = l1; *(__nv_bfloat162*)(Cl + off) = t;
                }
            }
        }
    }
}

// ---------------- fp32 -> (hi, lo) bf16 split (flat 1D grid, no waste) ------
// inputs: 6 x 16384 blocks; weights: 6 x 1024 blocks. total 104448.
#define SPLIT_IN_BLKS  (PLANE / 4 / 256)        // 16384
#define SPLIT_W_BLKS   (DD_ * DD_ / 4 / 256)    // 1024
#define SPLIT_TOTAL    (6 * SPLIT_IN_BLKS + 6 * SPLIT_W_BLKS)

struct SplitArgs12 { const float4* src[12]; };   // 0-5 inputs, 6-11 weights

__global__ __launch_bounds__(256) void split12_k(SplitArgs12 sa) {
    const int b = blockIdx.x;
    int job, i;
    bf *h, *l;
    if (b < 6 * SPLIT_IN_BLKS) {
        job = b >> 14;                    // /16384
        i = (b & (SPLIT_IN_BLKS - 1)) * 256 + threadIdx.x;
        h = g_xh[job]; l = g_xl[job];
    } else {
        const int b2 = b - 6 * SPLIT_IN_BLKS;
        job = 6 + (b2 >> 10);             // /1024
        i = (b2 & (SPLIT_W_BLKS - 1)) * 256 + threadIdx.x;
        h = g_wh[job - 6]; l = g_wl[job - 6];
    }
    const float4 v = sa.src[job][i];
    bf h0 = __float2bfloat16_rn(v.x), h1 = __float2bfloat16_rn(v.y);
    bf h2 = __float2bfloat16_rn(v.z), h3 = __float2bfloat16_rn(v.w);
    bf l0 = __float2bfloat16_rn(v.x - __bfloat162float(h0));
    bf l1 = __float2bfloat16_rn(v.y - __bfloat162float(h1));
    bf l2 = __float2bfloat16_rn(v.z - __bfloat162float(h2));
    bf l3 = __float2bfloat16_rn(v.w - __bfloat162float(h3));
    __nv_bfloat162 t;
    t.x = h0; t.y = h1; *(__nv_bfloat162*)(h + 4 * (size_t)i)     = t;
    t.x = h2; t.y = h3; *(__nv_bfloat162*)(h + 4 * (size_t)i + 2) = t;
    t.x = l0; t.y = l1; *(__nv_bfloat162*)(l + 4 * (size_t)i)     = t;
    t.x = l2; t.y = l3; *(__nv_bfloat162*)(l + 4 * (size_t)i + 2) = t;
}

// ---------------- batched 1024x1024 bf16 transpose (kr, vr, vi hi+lo) -------
__global__ __launch_bounds__(256) void transpose_k() {
    const int z = blockIdx.z, t = z >> 4, b = z & 15;
    const int si = (t == 0) ? 2 : (t == 1 ? 4 : 5);
    const bf* sh = g_ph[si] + (size_t)b * BATSTR;
    const bf* sl = g_pl[si] + (size_t)b * BATSTR;
    bf* dh = g_th[t] + (size_t)b * BATSTR;
    bf* dl = g_tl[t] + (size_t)b * BATSTR;
    __shared__ bf Th[32][33], Tl[32][33];
    const int tx = threadIdx.x, ty = threadIdx.y;
    const int x0 = blockIdx.x * 32, y0 = blockIdx.y * 32;
    #pragma unroll
    for (int j = ty; j < 32; j += 8) {
        Th[j][tx] = sh[(size_t)(y0 + j) * 1024 + x0 + tx];
        Tl[j][tx] = sl[(size_t)(y0 + j) * 1024 + x0 + tx];
    }
    __syncthreads();
    #pragma unroll
    for (int j = ty; j < 32; j += 8) {
        dh[(size_t)(x0 + j) * 1024 + y0 + tx] = Th[tx][j];
        dl[(size_t)(x0 + j) * 1024 + y0 + tx] = Tl[tx][j];
    }
}

// ---------------- softmax (scale 0.125 folded) -> split bf16 -----------------
__global__ __launch_bounds__(256) void softmax_k() {
    __shared__ float red[8];
    const size_t rowo = (size_t)blockIdx.x * 1024;
    const float* p = g_att + rowo;
    const int tid = threadIdx.x;

    float4 v = ((const float4*)p)[tid];
    v.x *= 0.125f; v.y *= 0.125f; v.z *= 0.125f; v.w *= 0.125f;

    float m = fmaxf(fmaxf(v.x, v.y), fmaxf(v.z, v.w));
    #pragma unroll
    for (int o = 16; o; o >>= 1) m = fmaxf(m, __shfl_xor_sync(0xffffffffu, m, o));
    if ((tid & 31) == 0) red[tid >> 5] = m;
    __syncthreads();
    float M = red[0];
    #pragma unroll
    for (int i = 1; i < 8; i++) M = fmaxf(M, red[i]);
    __syncthreads();

    v.x = __expf(v.x - M); v.y = __expf(v.y - M);
    v.z = __expf(v.z - M); v.w = __expf(v.w - M);
    float s = v.x + v.y + v.z + v.w;
    #pragma unroll
    for (int o = 16; o; o >>= 1) s += __shfl_xor_sync(0xffffffffu, s, o);
    if ((tid & 31) == 0) red[tid >> 5] = s;
    __syncthreads();
    float Tt = 0.f;
    #pragma unroll
    for (int i = 0; i < 8; i++) Tt += red[i];
    const float inv = 1.0f / Tt;
    v.x *= inv; v.y *= inv; v.z *= inv; v.w *= inv;

    bf h0 = __float2bfloat16_rn(v.x), h1 = __float2bfloat16_rn(v.y);
    bf h2 = __float2bfloat16_rn(v.z), h3 = __float2bfloat16_rn(v.w);
    bf l0 = __float2bfloat16_rn(v.x - __bfloat162float(h0));
    bf l1 = __float2bfloat16_rn(v.y - __bfloat162float(h1));
    bf l2 = __float2bfloat16_rn(v.z - __bfloat162float(h2));
    bf l3 = __float2bfloat16_rn(v.w - __bfloat162float(h3));
    const size_t o4 = rowo + (size_t)tid * 4;
    __nv_bfloat162 t;
    t.x = h0; t.y = h1; *(__nv_bfloat162*)(g_ah + o4)     = t;
    t.x = h2; t.y = h3; *(__nv_bfloat162*)(g_ah + o4 + 2) = t;
    t.x = l0; t.y = l1; *(__nv_bfloat162*)(g_al + o4)     = t;
    t.x = l2; t.y = l3; *(__nv_bfloat162*)(g_al + o4 + 2) = t;
}

// ---------------- complex LayerNorm + writeback ------------------------------
__global__ __launch_bounds__(256) void lnorm_k(const float* __restrict__ a2,
                                               const float* __restrict__ b2,
                                               float* __restrict__ out) {
    __shared__ float red[5][8];
    const size_t row = blockIdx.x;
    const int tid = threadIdx.x;
    const float4 ar = ((const float4*)(g_or + row * 1024))[tid];
    const float4 ai = ((const float4*)(g_oi + row * 1024))[tid];

    float sr  = ar.x + ar.y + ar.z + ar.w;
    float si  = ai.x + ai.y + ai.z + ai.w;
    float srr = ar.x*ar.x + ar.y*ar.y + ar.z*ar.z + ar.w*ar.w;
    float sii = ai.x*ai.x + ai.y*ai.y + ai.z*ai.z + ai.w*ai.w;
    float sri = ar.x*ai.x + ar.y*ai.y + ar.z*ai.z + ar.w*ai.w;
    #pragma unroll
    for (int o = 16; o; o >>= 1) {
        sr  += __shfl_xor_sync(0xffffffffu, sr,  o);
        si  += __shfl_xor_sync(0xffffffffu, si,  o);
        srr += __shfl_xor_sync(0xffffffffu, srr, o);
        sii += __shfl_xor_sync(0xffffffffu, sii, o);
        sri += __shfl_xor_sync(0xffffffffu, sri, o);
    }
    if ((tid & 31) == 0) {
        const int w = tid >> 5;
        red[0][w] = sr; red[1][w] = si; red[2][w] = srr;
        red[3][w] = sii; red[4][w] = sri;
    }
    __syncthreads();
    float Sr = 0, Si = 0, Srr = 0, Sii = 0, Sri = 0;
    #pragma unroll
    for (int i = 0; i < 8; i++) {
        Sr += red[0][i]; Si += red[1][i]; Srr += red[2][i];
        Sii += red[3][i]; Sri += red[4][i];
    }
    const float invD = 1.0f / 1024.0f;
    const float mr = Sr * invD, mi = Si * invD;
    const float vr = (Srr * invD - mr * mr) - (Sii * invD - mi * mi) + 1e-6f;
    const float vi = 2.0f * (Sri * invD - mr * mi);
    const float rad = sqrtf(vr * vr + vi * vi);
    const float c  = sqrtf(fmaxf(0.5f * (rad + vr), 0.0f));
    const float dd = copysignf(sqrtf(fmaxf(0.5f * (rad - vr), 0.0f)), vi);
    const float inv = 1.0f / (c * c + dd * dd);

    const int d0 = tid * 4;
    const float4 A2 = ((const float4*)a2)[tid];
    const float4 B2 = ((const float4*)b2)[tid];
    float4 yr, yi;
    { float wr = ar.x - mr, wi = ai.x - mi;
      yr.x = (wr*c + wi*dd)*inv*A2.x + B2.x; yi.x = (wi*c - wr*dd)*inv*A2.x; }
    { float wr = ar.y - mr, wi = ai.y - mi;
      yr.y = (wr*c + wi*dd)*inv*A2.y + B2.y; yi.y = (wi*c - wr*dd)*inv*A2.y; }
    { float wr = ar.z - mr, wi = ai.z - mi;
      yr.z = (wr*c + wi*dd)*inv*A2.z + B2.z; yi.z = (wi*c - wr*dd)*inv*A2.z; }
    { float wr = ar.w - mr, wi = ai.w - mi;
      yr.w = (wr*c + wi*dd)*inv*A2.w + B2.w; yi.w = (wi*c - wr*dd)*inv*A2.w; }
    *(float4*)&out[row * 1024 + d0] = yr;
    *(float4*)&out[(size_t)PLANE + row * 1024 + d0] = yi;
}

// ---------------------------------------------------------------------------
extern "C" void kernel_launch(void* const* d_in, const int* in_sizes, int n_in,
                              void* d_out, int out_size) {
    (void)in_sizes; (void)n_in; (void)out_size;
    cudaFuncSetAttribute(gemm_k<0>, cudaFuncAttributeMaxDynamicSharedMemorySize, DSM_BYTES);
    cudaFuncSetAttribute(gemm_k<1>, cudaFuncAttributeMaxDynamicSharedMemorySize, DSM_BYTES);
    cudaFuncSetAttribute(gemm_k<2>, cudaFuncAttributeMaxDynamicSharedMemorySize, DSM_BYTES);

    SplitArgs12 sp;
    BiasArr ba, bz = {};
    for (int j = 0; j < 6; j++) {
        sp.src[j]     = (const float4*)d_in[j];           // inputs
        sp.src[6 + j] = (const float4*)d_in[6 + 2 * j];   // weights
        ba.b[j]       = (const float*)d_in[7 + 2 * j];
    }
    // ncu empirically captures launch #4 -> scores GEMM
    // 1: all 12 splits (flat grid, exact sizing)
    split12_k<<<SPLIT_TOTAL, 256>>>(sp);
    // 2: all 6 projections (X @ W^T + b) -> split bf16
    gemm_k<0><<<dim3(8, 128, 6), 256, DSM_BYTES>>>(ba);
    // 3: transpose kr, vr, vi (hi+lo) per batch
    transpose_k<<<dim3(32, 32, 48), dim3(32, 8)>>>();
    // 4: scores = qr@krT + qi@ki^T  (fp32)   <-- ncu target
    gemm_k<1><<<dim3(8, 8, 16), 256, DSM_BYTES>>>(bz);
    // 5: softmax (+0.125 scale) -> split bf16 attn
    softmax_k<<<MTOT, 256>>>();
    // 6: out_r = attn@vr AND out_i = attn@vi (merged, grid.z=32)
    gemm_k<2><<<dim3(8, 8, 32), 256, DSM_BYTES>>>(bz);
    // 7: complex LayerNorm -> [2,B,S,D]
    lnorm_k<<<MTOT, 256>>>((const float*)d_in[18], (const float*)d_in[19], (float*)d_out);
}